// round 2
// baseline (speedup 1.0000x reference)
#include <cuda_runtime.h>
#include <stdint.h>

// FieldAwareFM: B=16384 samples, F=10 fields, D=8.
// out[b] = b_lin + sum_f w[idx_f] + sum_{f<g} <emb[f][idx_g], emb[g][idx_f]>
//
// Warp-per-sample, wavefront-coalesced gather layout:
//   round t (0..5), lane = 4*q + 2*role + half, q = pair-slot-in-round
//   slot p = 8*t + q selects pair (f,g); role 0 loads emb[f][idx_g],
//   role 1 loads emb[g][idx_f]; half selects which float4 of the 32B row.
//   Adjacent lanes (half 0/1) hit the same 128B line -> 1 L1 wavefront/row.
//   Dot product: shfl_xor by 2 swaps roles; every pair dot is computed twice,
//   compensated by a final *0.5.

#define BATCH      16384
#define NUM_FIELDS 10
#define FACTOR_DIM 8
#define INPUT_DIM  188610
#define NUM_PAIRS  45
#define NUM_SLOTS  48
#define NUM_ROUNDS 6

__constant__ int c_offsets[NUM_FIELDS] = {
    0, 100000, 150000, 170000, 180000, 185000, 187000, 188000, 188500, 188600
};

// c_tbl[2p + role]: low nibble = row table index, high nibble = column field
// role 0: (g<<4)|f   (load emb[f][idx_g])
// role 1: (f<<4)|g   (load emb[g][idx_f])
__constant__ unsigned char c_tbl[2 * NUM_SLOTS] = {
    0x10,0x01, 0x20,0x02, 0x30,0x03, 0x40,0x04, 0x50,0x05, 0x60,0x06, 0x70,0x07, 0x80,0x08,
    0x90,0x09, 0x21,0x12, 0x31,0x13, 0x41,0x14, 0x51,0x15, 0x61,0x16, 0x71,0x17, 0x81,0x18,
    0x91,0x19, 0x32,0x23, 0x42,0x24, 0x52,0x25, 0x62,0x26, 0x72,0x27, 0x82,0x28, 0x92,0x29,
    0x43,0x34, 0x53,0x35, 0x63,0x36, 0x73,0x37, 0x83,0x38, 0x93,0x39, 0x54,0x45, 0x64,0x46,
    0x74,0x47, 0x84,0x48, 0x94,0x49, 0x65,0x56, 0x75,0x57, 0x85,0x58, 0x95,0x59, 0x76,0x67,
    0x86,0x68, 0x96,0x69, 0x87,0x78, 0x97,0x79, 0x98,0x89, 0x00,0x00, 0x00,0x00, 0x00,0x00
};

__global__ __launch_bounds__(256)
void ffm_kernel(const int* __restrict__ x,
                const float* __restrict__ w,
                const float* __restrict__ b_lin,
                const float* __restrict__ emb,
                float* __restrict__ out)
{
    const int warp_in_block = threadIdx.x >> 5;
    const int lane          = threadIdx.x & 31;
    const int b             = blockIdx.x * (blockDim.x >> 5) + warp_in_block;
    const unsigned full     = 0xffffffffu;

    // per-lane slot decode entries (one-time divergent constant reads)
    unsigned char tbl6[NUM_ROUNDS];
#pragma unroll
    for (int t = 0; t < NUM_ROUNDS; t++) {
        tbl6[t] = c_tbl[((t * 8 + (lane >> 2)) << 1) | ((lane >> 1) & 1)];
    }

    // lanes 0..9: this sample's global indices (coalesced 40B load)
    int my_idx = 0;
    float lin  = 0.0f;
    if (lane < NUM_FIELDS) {
        my_idx = x[b * NUM_FIELDS + lane] + c_offsets[lane];
        lin    = __ldg(&w[my_idx]);
    }

    float ffm = 0.0f;

#pragma unroll
    for (int t = 0; t < NUM_ROUNDS; t++) {
        const int e   = (int)tbl6[t];
        const int row = e & 15;        // embedding table index
        const int col = e >> 4;        // field whose index we gather with
        const int idx = __shfl_sync(full, my_idx, col);
        const bool valid = (t * 8 + (lane >> 2)) < NUM_PAIRS;

        float4 v = make_float4(0.f, 0.f, 0.f, 0.f);
        if (valid) {
            const float4* __restrict__ p = (const float4*)
                (emb + ((size_t)row * INPUT_DIM + (size_t)idx) * FACTOR_DIM) + (lane & 1);
            v = __ldg(p);
        }
        // partner lane (role flipped) holds the matching half of the dual row
        float4 u;
        u.x = __shfl_xor_sync(full, v.x, 2);
        u.y = __shfl_xor_sync(full, v.y, 2);
        u.z = __shfl_xor_sync(full, v.z, 2);
        u.w = __shfl_xor_sync(full, v.w, 2);
        ffm += v.x * u.x + v.y * u.y + v.z * u.z + v.w * u.w;
    }

    // every pair dot counted twice across the role pair -> *0.5
    float acc = 0.5f * ffm + lin;

#pragma unroll
    for (int off = 16; off > 0; off >>= 1) {
        acc += __shfl_xor_sync(full, acc, off);
    }

    if (lane == 0) {
        out[b] = acc + __ldg(&b_lin[0]);
    }
}

extern "C" void kernel_launch(void* const* d_in, const int* in_sizes, int n_in,
                              void* d_out, int out_size)
{
    (void)in_sizes; (void)n_in; (void)out_size;
    const int*   x     = (const int*)d_in[0];
    const float* w     = (const float*)d_in[1];
    const float* b_lin = (const float*)d_in[2];
    const float* emb   = (const float*)d_in[3];
    float*       out   = (float*)d_out;

    const int warps_per_block = 8;              // 256 threads
    const int blocks = BATCH / warps_per_block; // 2048
    ffm_kernel<<<blocks, warps_per_block * 32>>>(x, w, b_lin, emb, out);
}